// round 4
// baseline (speedup 1.0000x reference)
#include <cuda_runtime.h>
#include <cstdint>

// Fixed problem maxima (from reference): 1M edges, 100K nodes, 2M pairs.
#define NE_MAX 1000000
#define NN_MAX 100000

// Scratch: allocation-free rule -> __device__ globals.
__device__ float g_P[(size_t)NE_MAX * 64];   // edge_attr @ W_edge[:, :64]^T
__device__ float g_Q[(size_t)NN_MAX * 64];   // [x|gs]    @ W_edge[:, 64:]^T

typedef unsigned long long u64;

__device__ __forceinline__ float eluf(float x) {
    return x > 0.f ? x : (__expf(x) - 1.f);
}
__device__ __forceinline__ u64 dup2(float v) {
    u64 r; asm("mov.b64 %0, {%1, %1};" : "=l"(r) : "f"(v)); return r;
}
__device__ __forceinline__ void fma2(u64& d, u64 a, u64 b) {
    asm("fma.rn.f32x2 %0, %1, %2, %0;" : "+l"(d) : "l"(a), "l"(b));
}
__device__ __forceinline__ float2 unpack2(u64 v) {
    float2 f; asm("mov.b64 {%0, %1}, %2;" : "=f"(f.x), "=f"(f.y) : "l"(v)); return f;
}

// ---------------------------------------------------------------------------
// K1: Q = xg @ W_edge[:, 64:106]^T   (M=NN, N=64, K=42) — tiled mini-GEMM.
// Block tile: 128 nodes x 64 cols, 256 threads, 4x8 register tile each.
// ---------------------------------------------------------------------------
__global__ __launch_bounds__(256) void node_proj_kernel(
    const float* __restrict__ x,
    const float* __restrict__ gs,
    const float* __restrict__ W_edge,
    int NN) {
    __shared__ float Xs[42][132];   // [k][node], padded
    __shared__ float Wn[42][64];    // [k][o]

    int tid = threadIdx.x;
    int n0  = blockIdx.x * 128;

    for (int s = tid; s < 64 * 42; s += 256) {
        int o = s / 42, i = s % 42;
        Wn[i][o] = W_edge[o * 106 + 64 + i];
    }
    for (int s = tid; s < 128 * 37; s += 256) {
        int nl = s / 37, i = s % 37;
        float v = (n0 + nl < NN) ? x[(size_t)n0 * 37 + s] : 0.f;
        Xs[i][nl] = v;
    }
    for (int s = tid; s < 128 * 5; s += 256) {
        int nl = s / 5, j = s % 5;
        float v = (n0 + nl < NN) ? gs[(size_t)n0 * 5 + s] : 0.f;
        Xs[37 + j][nl] = v;
    }
    __syncthreads();

    int tr = tid >> 3;   // 0..31 -> node rows tr*4..+3
    int tc = tid & 7;    // 0..7  -> cols tc*8..+7

    float acc[4][8];
#pragma unroll
    for (int r = 0; r < 4; r++)
#pragma unroll
        for (int c = 0; c < 8; c++) acc[r][c] = 0.f;

#pragma unroll 6
    for (int k = 0; k < 42; k++) {
        float a[4], w[8];
        *(float4*)a       = *(const float4*)&Xs[k][tr * 4];
        *(float4*)w       = *(const float4*)&Wn[k][tc * 8];
        *(float4*)(w + 4) = *(const float4*)&Wn[k][tc * 8 + 4];
#pragma unroll
        for (int r = 0; r < 4; r++)
#pragma unroll
            for (int c = 0; c < 8; c++)
                acc[r][c] = fmaf(a[r], w[c], acc[r][c]);
    }

#pragma unroll
    for (int r = 0; r < 4; r++) {
        int n = n0 + tr * 4 + r;
        if (n < NN) {
            *(float4*)&g_Q[(size_t)n * 64 + tc * 8]     = *(float4*)&acc[r][0];
            *(float4*)&g_Q[(size_t)n * 64 + tc * 8 + 4] = *(float4*)&acc[r][4];
        }
    }
}

// ---------------------------------------------------------------------------
// K2: combined GEMM  [NE,64] x [64,128] with packed f32x2 FMA:
//   cols   0..63  -> out  = elu(E @ W_e^T + b_e)
//   cols  64..127 -> g_P  = E @ W_edge[:, :64]^T
// 128x128 block tile, 128 threads, 8 rows x 16 cols per thread.
// A tile row-major with stride 65 (odd -> conflict-free column reads).
// ---------------------------------------------------------------------------
#define SAS2 65

__global__ __launch_bounds__(128, 2) void edge_gemm_kernel(
    const float* __restrict__ E,
    const float* __restrict__ W_edge,
    const float* __restrict__ W_e,
    const float* __restrict__ b_e,
    float* __restrict__ out,
    int NE) {
    extern __shared__ float sm[];
    float* As = sm;                 // [128][SAS2]  row-major A tile
    float* Ws = sm + 128 * SAS2;    // [64][128]    transposed weights: Ws[k][o]

    int tid = threadIdx.x;

    // Stage combined weights once (persistent grid amortizes).
    for (int s = tid; s < 64 * 128; s += 128) {
        int k = s >> 7, o = s & 127;
        Ws[k * 128 + o] = (o < 64) ? W_e[o * 64 + k] : W_edge[(o - 64) * 106 + k];
    }

    int tr = tid >> 3;   // 0..15 -> rows tr*8..+7
    int tc = tid & 7;    // 0..7  -> cols tc*16..+15

    // Bias registers for the out half (tc < 4), hoisted across tiles.
    float bb[16];
    if (tc < 4) {
#pragma unroll
        for (int j = 0; j < 16; j++) bb[j] = __ldg(&b_e[tc * 16 + j]);
    }

    int ntiles = (NE + 127) >> 7;
    for (int t = blockIdx.x; t < ntiles; t += gridDim.x) {
        int row0 = t << 7;
        __syncthreads();   // protect As from previous tile's readers (covers Ws on t0)

        // Stage A tile row-major: As[r][k], stride 65
#pragma unroll
        for (int i = 0; i < 16; i++) {
            int s  = tid + i * 128;
            int r  = s >> 4, kq = s & 15;
            int row = row0 + r;
            float4 v = make_float4(0.f, 0.f, 0.f, 0.f);
            if (row < NE) v = *(const float4*)&E[(size_t)row * 64 + kq * 4];
            As[r * SAS2 + kq * 4 + 0] = v.x;
            As[r * SAS2 + kq * 4 + 1] = v.y;
            As[r * SAS2 + kq * 4 + 2] = v.z;
            As[r * SAS2 + kq * 4 + 3] = v.w;
        }
        __syncthreads();

        u64 acc2[64];
#pragma unroll
        for (int i = 0; i < 64; i++) acc2[i] = 0ull;

        const float* arow = As + tr * 8 * SAS2;
        const float* wrow = Ws + tc * 16;

#pragma unroll 4
        for (int k = 0; k < 64; k++) {
            float a[8];
#pragma unroll
            for (int i = 0; i < 8; i++) a[i] = arow[i * SAS2 + k];

            ulonglong2 w01 = *(const ulonglong2*)&wrow[k * 128];
            ulonglong2 w23 = *(const ulonglong2*)&wrow[k * 128 + 4];
            ulonglong2 w45 = *(const ulonglong2*)&wrow[k * 128 + 8];
            ulonglong2 w67 = *(const ulonglong2*)&wrow[k * 128 + 12];
            u64 wp[8] = {w01.x, w01.y, w23.x, w23.y, w45.x, w45.y, w67.x, w67.y};
#pragma unroll
            for (int i = 0; i < 8; i++) {
                u64 ad = dup2(a[i]);
#pragma unroll
                for (int j = 0; j < 8; j++)
                    fma2(acc2[i * 8 + j], ad, wp[j]);
            }
        }

        if (tc < 4) {
            // out half: cols tc*16..+15 — add bias, elu
            int c0 = tc * 16;
#pragma unroll
            for (int i = 0; i < 8; i++) {
                int row = row0 + tr * 8 + i;
                if (row < NE) {
                    float v[16];
#pragma unroll
                    for (int jp = 0; jp < 8; jp++) {
                        float2 c = unpack2(acc2[i * 8 + jp]);
                        v[jp * 2]     = eluf(c.x + bb[jp * 2]);
                        v[jp * 2 + 1] = eluf(c.y + bb[jp * 2 + 1]);
                    }
                    float* o = &out[(size_t)row * 64 + c0];
#pragma unroll
                    for (int q = 0; q < 4; q++)
                        *(float4*)(o + q * 4) = *(float4*)(v + q * 4);
                }
            }
        } else {
            // P half: cols tc*16-64..+15 raw
            int c0 = tc * 16 - 64;
#pragma unroll
            for (int i = 0; i < 8; i++) {
                int row = row0 + tr * 8 + i;
                if (row < NE) {
                    float* p = &g_P[(size_t)row * 64 + c0];
#pragma unroll
                    for (int q = 0; q < 4; q++) {
                        ulonglong2 s2;
                        s2.x = acc2[i * 8 + q * 2];
                        s2.y = acc2[i * 8 + q * 2 + 1];
                        *(ulonglong2*)(p + q * 4) = s2;
                    }
                }
            }
        }
    }
}

// ---------------------------------------------------------------------------
// K3: per pair k:  h = elu(P[e1] + Q[a0] + b_edge);  out[e0] += h
// 16 threads per pair, float4 lanes, vector red.global scatter.
// ---------------------------------------------------------------------------
__global__ void pair_scatter_kernel(const float* __restrict__ b_edge,
                                    const int* __restrict__ aidx,
                                    const int* __restrict__ eidx,
                                    float* __restrict__ out,
                                    int NP) {
    __shared__ float bs[64];
    int tid = threadIdx.x;
    if (tid < 64) bs[tid] = b_edge[tid];
    __syncthreads();

    int pl = tid >> 4;
    int q  = tid & 15;
    long long k = (long long)blockIdx.x * 16 + pl;
    if (k >= NP) return;

    int e0 = eidx[k];
    int e1 = eidx[(size_t)NP + k];
    int a0 = aidx[k];

    float4 p  = __ldg((const float4*)&g_P[(size_t)e1 * 64 + q * 4]);
    float4 qv = __ldg((const float4*)&g_Q[(size_t)a0 * 64 + q * 4]);

    float h0 = eluf(p.x + qv.x + bs[q * 4 + 0]);
    float h1 = eluf(p.y + qv.y + bs[q * 4 + 1]);
    float h2 = eluf(p.z + qv.z + bs[q * 4 + 2]);
    float h3 = eluf(p.w + qv.w + bs[q * 4 + 3]);

    float* addr = out + (size_t)e0 * 64 + q * 4;
    asm volatile("red.global.add.v4.f32 [%0], {%1,%2,%3,%4};"
                 :: "l"(addr), "f"(h0), "f"(h1), "f"(h2), "f"(h3)
                 : "memory");
}

// ---------------------------------------------------------------------------
extern "C" void kernel_launch(void* const* d_in, const int* in_sizes, int n_in,
                              void* d_out, int out_size) {
    const float* x      = (const float*)d_in[0];
    const float* gs     = (const float*)d_in[1];
    const float* E      = (const float*)d_in[2];
    const float* W_edge = (const float*)d_in[3];
    const float* b_edge = (const float*)d_in[4];
    const float* W_e    = (const float*)d_in[5];
    const float* b_e    = (const float*)d_in[6];
    const int*   aidx   = (const int*)d_in[7];
    const int*   eidx   = (const int*)d_in[8];
    float* out = (float*)d_out;

    int NN = in_sizes[0] / 37;
    int NE = in_sizes[2] / 64;
    int NP = in_sizes[7] / 2;
    if (NN > NN_MAX) NN = NN_MAX;
    if (NE > NE_MAX) NE = NE_MAX;

    // K1: node projections -> g_Q
    node_proj_kernel<<<(NN + 127) / 128, 256>>>(x, gs, W_edge, NN);

    // K2: fused edge GEMM -> out (elu half) + g_P
    const int smem_bytes = (128 * SAS2 + 64 * 128) * (int)sizeof(float);  // 66048
    cudaFuncSetAttribute(edge_gemm_kernel,
                         cudaFuncAttributeMaxDynamicSharedMemorySize, smem_bytes);
    edge_gemm_kernel<<<296, 128, smem_bytes>>>(E, W_edge, W_e, b_e, out, NE);

    // K3: pair gather + elu + vector-red scatter (direct — fastest measured)
    int t3 = (NP + 15) / 16;
    pair_scatter_kernel<<<t3, 256>>>(b_edge, aidx, eidx, out, NP);
}

// round 6
// speedup vs baseline: 1.7026x; 1.7026x over previous
#include <cuda_runtime.h>
#include <cuda_bf16.h>
#include <cstdint>

// Fixed problem maxima (from reference): 1M edges, 100K nodes, 2M pairs.
#define NE_MAX 1000000
#define NN_MAX 100000

__device__ float g_P[(size_t)NE_MAX * 64];   // edge_attr @ W_edge[:, :64]^T
__device__ float g_Q[(size_t)NN_MAX * 64];   // [x|gs]    @ W_edge[:, 64:]^T

__device__ __forceinline__ float eluf(float x) {
    return x > 0.f ? x : (__expf(x) - 1.f);
}
__device__ __forceinline__ uint32_t smem_u32(const void* p) {
    uint32_t a;
    asm("{ .reg .u64 t; cvta.to.shared.u64 t, %1; cvt.u32.u64 %0, t; }" : "=r"(a) : "l"(p));
    return a;
}
// pack two floats to bf16x2 (lo -> low 16 bits, matching memory order)
__device__ __forceinline__ uint32_t pack_bf(float lo, float hi) {
    uint32_t r; asm("cvt.rn.bf16x2.f32 %0, %1, %2;" : "=r"(r) : "f"(hi), "f"(lo)); return r;
}
__device__ __forceinline__ void ldm_x4(uint32_t* r, uint32_t addr) {
    asm volatile("ldmatrix.sync.aligned.m8n8.x4.shared.b16 {%0,%1,%2,%3}, [%4];"
                 : "=r"(r[0]), "=r"(r[1]), "=r"(r[2]), "=r"(r[3]) : "r"(addr));
}
__device__ __forceinline__ void mma_bf16(float* d, const uint32_t* a, uint32_t b0, uint32_t b1) {
    asm volatile(
        "mma.sync.aligned.m16n8k16.row.col.f32.bf16.bf16.f32 "
        "{%0,%1,%2,%3}, {%4,%5,%6,%7}, {%8,%9}, {%0,%1,%2,%3};"
        : "+f"(d[0]), "+f"(d[1]), "+f"(d[2]), "+f"(d[3])
        : "r"(a[0]), "r"(a[1]), "r"(a[2]), "r"(a[3]), "r"(b0), "r"(b1));
}
// split a float4 into bf16x2 hi words + residual lo words, store to smem
__device__ __forceinline__ void split_store(char* dhi, char* dlo, float4 v) {
    uint32_t h0 = pack_bf(v.x, v.y);
    uint32_t l0 = pack_bf(v.x - __uint_as_float(h0 << 16),
                          v.y - __uint_as_float(h0 & 0xFFFF0000u));
    uint32_t h1 = pack_bf(v.z, v.w);
    uint32_t l1 = pack_bf(v.z - __uint_as_float(h1 << 16),
                          v.w - __uint_as_float(h1 & 0xFFFF0000u));
    *(uint32_t*)(dhi)     = h0;
    *(uint32_t*)(dhi + 4) = h1;
    *(uint32_t*)(dlo)     = l0;
    *(uint32_t*)(dlo + 4) = l1;
}

// ---------------------------------------------------------------------------
// K1: Q = xg @ W_edge[:, 64:106]^T   (M=NN, N=64, K=42) — tiled mini-GEMM.
// ---------------------------------------------------------------------------
__global__ __launch_bounds__(256) void node_proj_kernel(
    const float* __restrict__ x,
    const float* __restrict__ gs,
    const float* __restrict__ W_edge,
    int NN) {
    __shared__ float Xs[42][132];
    __shared__ float Wn[42][64];

    int tid = threadIdx.x;
    int n0  = blockIdx.x * 128;

    for (int s = tid; s < 64 * 42; s += 256) {
        int o = s / 42, i = s % 42;
        Wn[i][o] = W_edge[o * 106 + 64 + i];
    }
    for (int s = tid; s < 128 * 37; s += 256) {
        int nl = s / 37, i = s % 37;
        float v = (n0 + nl < NN) ? x[(size_t)n0 * 37 + s] : 0.f;
        Xs[i][nl] = v;
    }
    for (int s = tid; s < 128 * 5; s += 256) {
        int nl = s / 5, j = s % 5;
        float v = (n0 + nl < NN) ? gs[(size_t)n0 * 5 + s] : 0.f;
        Xs[37 + j][nl] = v;
    }
    __syncthreads();

    int tr = tid >> 3, tc = tid & 7;
    float acc[4][8];
#pragma unroll
    for (int r = 0; r < 4; r++)
#pragma unroll
        for (int c = 0; c < 8; c++) acc[r][c] = 0.f;

#pragma unroll 6
    for (int k = 0; k < 42; k++) {
        float a[4], w[8];
        *(float4*)a       = *(const float4*)&Xs[k][tr * 4];
        *(float4*)w       = *(const float4*)&Wn[k][tc * 8];
        *(float4*)(w + 4) = *(const float4*)&Wn[k][tc * 8 + 4];
#pragma unroll
        for (int r = 0; r < 4; r++)
#pragma unroll
            for (int c = 0; c < 8; c++)
                acc[r][c] = fmaf(a[r], w[c], acc[r][c]);
    }

#pragma unroll
    for (int r = 0; r < 4; r++) {
        int n = n0 + tr * 4 + r;
        if (n < NN) {
            *(float4*)&g_Q[(size_t)n * 64 + tc * 8]     = *(float4*)&acc[r][0];
            *(float4*)&g_Q[(size_t)n * 64 + tc * 8 + 4] = *(float4*)&acc[r][4];
        }
    }
}

// ---------------------------------------------------------------------------
// K2: bf16 3-term-split tensor GEMM via mma.sync  [NE,64] x [64,128]:
//   N cols 0..63  -> out = elu(E @ W_e^T + b_e)
//   N cols 64..127-> g_P = E @ W_edge[:, :64]^T
// 256 threads / 8 warps; per 128-row tile each warp computes 16 rows x 128 N.
// A,B staged as bf16 hi/lo in SMEM, row stride 72 bf16 (144B: ldmatrix
// conflict-free since 144 mod 128 = 16).
// ---------------------------------------------------------------------------
#define ASTRIDE 144
#define SM_AHI  0
#define SM_ALO  18432
#define SM_BHI  36864
#define SM_BLO  55296
#define SM_BIAS 73728
#define SM_TOT  (73728 + 256)

__global__ __launch_bounds__(256) void edge_gemm_mma_kernel(
    const float* __restrict__ E,
    const float* __restrict__ W_edge,
    const float* __restrict__ W_e,
    const float* __restrict__ b_e,
    float* __restrict__ out,
    int NE) {
    extern __shared__ char sm[];
    uint32_t smb = smem_u32(sm);
    int tid  = threadIdx.x;
    int wid  = tid >> 5;
    int lane = tid & 31;

    if (tid < 64) *(float*)(sm + SM_BIAS + tid * 4) = b_e[tid];

    // Convert combined weights (rows: 0..63 = W_e, 64..127 = W_edge[:, :64])
    for (int s = tid; s < 128 * 16; s += 256) {
        int o = s >> 4, q = s & 15;
        float4 v;
        if (o < 64) {
            v = *(const float4*)&W_e[o * 64 + q * 4];
        } else {
            const float* wr = &W_edge[(o - 64) * 106 + q * 4];
            v = make_float4(wr[0], wr[1], wr[2], wr[3]);
        }
        split_store(sm + SM_BHI + o * ASTRIDE + q * 8,
                    sm + SM_BLO + o * ASTRIDE + q * 8, v);
    }

    // per-lane ldmatrix source offsets
    int arow = (lane & 7) + ((lane >> 3) & 1) * 8;   // row within 16-slab
    int acol = (lane >> 4) * 8;                      // bf16 col 0 or 8
    uint32_t aoff = (uint32_t)((wid * 16 + arow) * ASTRIDE + acol * 2);
    int brow = lane & 7;
    int bk   = (lane >> 3) * 8;
    uint32_t boff = (uint32_t)(brow * ASTRIDE + bk * 2);

    int g  = lane >> 2;      // accum row within 8
    int tq = lane & 3;       // accum col pair

    int ntiles = (NE + 127) >> 7;
    for (int t = blockIdx.x; t < ntiles; t += gridDim.x) {
        int row0 = t << 7;
        __syncthreads();   // prior tile's A-fragment reads done (covers weights on t0)

        // Stage + convert A tile (128 rows x 64 k) to bf16 hi/lo
#pragma unroll
        for (int i = 0; i < 8; i++) {
            int s = tid + i * 256;
            int r = s >> 4, q = s & 15;
            int row = row0 + r;
            float4 v = make_float4(0.f, 0.f, 0.f, 0.f);
            if (row < NE) v = ((const float4*)(E + (size_t)row * 64))[q];
            split_store(sm + SM_AHI + r * ASTRIDE + q * 8,
                        sm + SM_ALO + r * ASTRIDE + q * 8, v);
        }
        __syncthreads();

        // Load A fragments for this warp's 16 rows (4 k-steps, hi+lo)
        uint32_t Ah[4][4], Al[4][4];
#pragma unroll
        for (int k = 0; k < 4; k++) {
            ldm_x4(Ah[k], smb + SM_AHI + aoff + k * 32);
            ldm_x4(Al[k], smb + SM_ALO + aoff + k * 32);
        }

        // N tiles: j = 0..15 (cols j*8..j*8+7)
#pragma unroll 2
        for (int j = 0; j < 16; j++) {
            uint32_t nb = (uint32_t)(j * 8 * ASTRIDE) + boff;
            uint32_t Bh[8], Bl[8];
            ldm_x4(Bh,     smb + SM_BHI + nb);        // k-steps 0,1
            ldm_x4(Bh + 4, smb + SM_BHI + nb + 64);   // k-steps 2,3
            ldm_x4(Bl,     smb + SM_BLO + nb);
            ldm_x4(Bl + 4, smb + SM_BLO + nb + 64);

            float acc[4] = {0.f, 0.f, 0.f, 0.f};
#pragma unroll
            for (int k = 0; k < 4; k++) {
                mma_bf16(acc, Ah[k], Bh[k * 2], Bh[k * 2 + 1]);
                mma_bf16(acc, Al[k], Bh[k * 2], Bh[k * 2 + 1]);
                mma_bf16(acc, Ah[k], Bl[k * 2], Bl[k * 2 + 1]);
            }

            int ra = row0 + wid * 16 + g;
            int rb = ra + 8;
            int c  = j * 8 + tq * 2;
            if (j < 8) {
                float2 bb = *(float2*)(sm + SM_BIAS + c * 4);
                if (ra < NE) {
                    float2 v = make_float2(eluf(acc[0] + bb.x), eluf(acc[1] + bb.y));
                    *(float2*)&out[(size_t)ra * 64 + c] = v;
                }
                if (rb < NE) {
                    float2 v = make_float2(eluf(acc[2] + bb.x), eluf(acc[3] + bb.y));
                    *(float2*)&out[(size_t)rb * 64 + c] = v;
                }
            } else {
                int cp = c - 64;
                if (ra < NE)
                    *(float2*)&g_P[(size_t)ra * 64 + cp] = make_float2(acc[0], acc[1]);
                if (rb < NE)
                    *(float2*)&g_P[(size_t)rb * 64 + cp] = make_float2(acc[2], acc[3]);
            }
        }
    }
}

// ---------------------------------------------------------------------------
// K3: per pair k:  h = elu(P[e1] + Q[a0] + b_edge);  out[e0] += h
// ---------------------------------------------------------------------------
__global__ void pair_scatter_kernel(const float* __restrict__ b_edge,
                                    const int* __restrict__ aidx,
                                    const int* __restrict__ eidx,
                                    float* __restrict__ out,
                                    int NP) {
    __shared__ float bs[64];
    int tid = threadIdx.x;
    if (tid < 64) bs[tid] = b_edge[tid];
    __syncthreads();

    int pl = tid >> 4;
    int q  = tid & 15;
    long long k = (long long)blockIdx.x * 16 + pl;
    if (k >= NP) return;

    int e0 = eidx[k];
    int e1 = eidx[(size_t)NP + k];
    int a0 = aidx[k];

    float4 p  = __ldg((const float4*)&g_P[(size_t)e1 * 64 + q * 4]);
    float4 qv = __ldg((const float4*)&g_Q[(size_t)a0 * 64 + q * 4]);

    float h0 = eluf(p.x + qv.x + bs[q * 4 + 0]);
    float h1 = eluf(p.y + qv.y + bs[q * 4 + 1]);
    float h2 = eluf(p.z + qv.z + bs[q * 4 + 2]);
    float h3 = eluf(p.w + qv.w + bs[q * 4 + 3]);

    float* addr = out + (size_t)e0 * 64 + q * 4;
    asm volatile("red.global.add.v4.f32 [%0], {%1,%2,%3,%4};"
                 :: "l"(addr), "f"(h0), "f"(h1), "f"(h2), "f"(h3)
                 : "memory");
}

// ---------------------------------------------------------------------------
extern "C" void kernel_launch(void* const* d_in, const int* in_sizes, int n_in,
                              void* d_out, int out_size) {
    const float* x      = (const float*)d_in[0];
    const float* gs     = (const float*)d_in[1];
    const float* E      = (const float*)d_in[2];
    const float* W_edge = (const float*)d_in[3];
    const float* b_edge = (const float*)d_in[4];
    const float* W_e    = (const float*)d_in[5];
    const float* b_e    = (const float*)d_in[6];
    const int*   aidx   = (const int*)d_in[7];
    const int*   eidx   = (const int*)d_in[8];
    float* out = (float*)d_out;

    int NN = in_sizes[0] / 37;
    int NE = in_sizes[2] / 64;
    int NP = in_sizes[7] / 2;
    if (NN > NN_MAX) NN = NN_MAX;
    if (NE > NE_MAX) NE = NE_MAX;

    node_proj_kernel<<<(NN + 127) / 128, 256>>>(x, gs, W_edge, NN);

    cudaFuncSetAttribute(edge_gemm_mma_kernel,
                         cudaFuncAttributeMaxDynamicSharedMemorySize, SM_TOT);
    edge_gemm_mma_kernel<<<296, 256, SM_TOT>>>(E, W_edge, W_e, b_e, out, NE);

    int t3 = (NP + 15) / 16;
    pair_scatter_kernel<<<t3, 256>>>(b_edge, aidx, eidx, out, NP);
}